// round 2
// baseline (speedup 1.0000x reference)
#include <cuda_runtime.h>

#define D_ 768
#define B_ 64
#define A_ 256
#define L_ 2
#define NG1 4
#define NG2 8

// Scratch (device globals; no allocation allowed)
__device__ float g_h1[NG1 * B_ * D_];     // [g1][b][d]
__device__ float g_M2[A_ * L_ * D_];      // [a][l][d]  (transposed for heads)
__device__ float g_c[A_ * L_];            // fused bias term: b2@Wh + bh
__device__ int   g_list[NG2][A_];
__device__ int   g_cnt[NG2];

__device__ __forceinline__ void ffma2(unsigned long long& acc,
                                      unsigned long long a,
                                      unsigned long long b) {
    asm("fma.rn.f32x2 %0, %1, %2, %0;" : "+l"(acc) : "l"(a), "l"(b));
}
__device__ __forceinline__ unsigned long long pack2(float lo, float hi) {
    unsigned long long r;
    asm("mov.b64 %0, {%1, %2};" : "=l"(r) : "f"(lo), "f"(hi));
    return r;
}
__device__ __forceinline__ void unpack2(unsigned long long v, float& lo, float& hi) {
    asm("mov.b64 {%0, %1}, %2;" : "=f"(lo), "=f"(hi) : "l"(v));
}

// ---------------------------------------------------------------------------
// Bin annotators by g2 (deterministic order: ascending a within each bin).
// ---------------------------------------------------------------------------
__global__ void bin_kernel(const int* __restrict__ g2i) {
    int g = threadIdx.x;
    if (g < NG2) {
        int c = 0;
        for (int a = 0; a < A_; a++)
            if (g2i[a] == g) g_list[g][c++] = a;
        g_cnt[g] = c;
    }
}

// ---------------------------------------------------------------------------
// c[a][l] = dot(b2[g2[a]], Wh[a][:,l]) + bh[a][l]
// ---------------------------------------------------------------------------
__global__ void __launch_bounds__(128) c_kernel(const float* __restrict__ b2,
                                                const float* __restrict__ Wh,
                                                const float* __restrict__ bh,
                                                const int* __restrict__ g2i) {
    const int a = blockIdx.x;
    const int t = threadIdx.x;
    const int g2 = g2i[a];
    const float* b2g = b2 + g2 * D_;
    const float* wha = Wh + a * (D_ * L_);

    float s0 = 0.f, s1 = 0.f;
    for (int e0 = t * 4; e0 < D_; e0 += 512) {
        float4 bv  = *(const float4*)(b2g + e0);
        float4 w01 = *(const float4*)(wha + e0 * 2);       // (e0,l0)(e0,l1)(e0+1,l0)(e0+1,l1)
        float4 w23 = *(const float4*)(wha + e0 * 2 + 4);
        s0 += bv.x * w01.x + bv.y * w01.z + bv.z * w23.x + bv.w * w23.z;
        s1 += bv.x * w01.y + bv.y * w01.w + bv.z * w23.y + bv.w * w23.w;
    }
#pragma unroll
    for (int o = 16; o; o >>= 1) {
        s0 += __shfl_down_sync(~0u, s0, o);
        s1 += __shfl_down_sync(~0u, s1, o);
    }
    __shared__ float red[4][2];
    int warp = t >> 5, lane = t & 31;
    if (lane == 0) { red[warp][0] = s0; red[warp][1] = s1; }
    __syncthreads();
    if (t == 0) {
        float a0 = red[0][0] + red[1][0] + red[2][0] + red[3][0];
        float a1 = red[0][1] + red[1][1] + red[2][1] + red[3][1];
        g_c[a * 2 + 0] = a0 + bh[a * 2 + 0];
        g_c[a * 2 + 1] = a1 + bh[a * 2 + 1];
    }
}

// ---------------------------------------------------------------------------
// Stage 1: h1[g][b][e] = sum_d pooled[b][d] * W1[g][d][e] + b1[g][e]
// Grid (24 n-tiles, 2 m-tiles, 4 g), 128 threads. Tile 32x32, K-chunk 16.
// Register prefetch double-buffer; B operand stored pre-duplicated for f32x2.
// ---------------------------------------------------------------------------
__global__ void __launch_bounds__(128) stage1_kernel(const float* __restrict__ pooled,
                                                     const float* __restrict__ W1,
                                                     const float* __restrict__ b1) {
    const int n0 = blockIdx.x * 32;
    const int m0 = blockIdx.y * 32;
    const int g  = blockIdx.z;
    const float* Wg = W1 + g * D_ * D_;

    __shared__ __align__(16) float As[16][34];    // [k][m], padded
    __shared__ __align__(16) float Wsd[16][64];   // [k][2n] duplicated pairs

    const int t  = threadIdx.x;
    const int mg = t >> 4;          // 0..7  (4 m-rows each)
    const int ng = t & 15;          // 0..15 (2 n-cols each)

    const int arow = t >> 2;        // 0..31
    const int akq  = (t & 3) * 4;   // 0,4,8,12
    const int wkr  = t >> 3;        // 0..15
    const int wnc  = (t & 7) * 4;   // 0..28

    const float* aptr = pooled + (m0 + arow) * D_ + akq;
    const float* wptr = Wg + wkr * D_ + n0 + wnc;

    float4 pa = *(const float4*)(aptr);
    float4 pw = *(const float4*)(wptr);

    unsigned long long acc00 = 0, acc01 = 0, acc10 = 0, acc11 = 0;

    for (int k0 = 0; k0 < D_; k0 += 16) {
        As[akq + 0][arow] = pa.x;
        As[akq + 1][arow] = pa.y;
        As[akq + 2][arow] = pa.z;
        As[akq + 3][arow] = pa.w;
        *(unsigned long long*)&Wsd[wkr][wnc * 2 + 0] = pack2(pw.x, pw.x);
        *(unsigned long long*)&Wsd[wkr][wnc * 2 + 2] = pack2(pw.y, pw.y);
        *(unsigned long long*)&Wsd[wkr][wnc * 2 + 4] = pack2(pw.z, pw.z);
        *(unsigned long long*)&Wsd[wkr][wnc * 2 + 6] = pack2(pw.w, pw.w);
        __syncthreads();
        if (k0 + 16 < D_) {
            pa = *(const float4*)(aptr + (k0 + 16));
            pw = *(const float4*)(wptr + (k0 + 16) * D_);
        }
#pragma unroll
        for (int kk = 0; kk < 16; kk++) {
            unsigned long long a0 = *(const unsigned long long*)&As[kk][mg * 4];
            unsigned long long a1 = *(const unsigned long long*)&As[kk][mg * 4 + 2];
            ulonglong2 bq = *(const ulonglong2*)&Wsd[kk][ng * 4];
            ffma2(acc00, a0, bq.x);
            ffma2(acc01, a0, bq.y);
            ffma2(acc10, a1, bq.x);
            ffma2(acc11, a1, bq.y);
        }
        __syncthreads();
    }

    const float bn0 = b1[g * D_ + n0 + ng * 2];
    const float bn1 = b1[g * D_ + n0 + ng * 2 + 1];
    float* Cb = g_h1 + g * B_ * D_;
    const int col = n0 + ng * 2;
    float lo, hi;
    int row = m0 + mg * 4;
    unpack2(acc00, lo, hi);
    Cb[row * D_ + col] = lo + bn0;       Cb[(row + 1) * D_ + col] = hi + bn0;
    unpack2(acc01, lo, hi);
    Cb[row * D_ + col + 1] = lo + bn1;   Cb[(row + 1) * D_ + col + 1] = hi + bn1;
    row += 2;
    unpack2(acc10, lo, hi);
    Cb[row * D_ + col] = lo + bn0;       Cb[(row + 1) * D_ + col] = hi + bn0;
    unpack2(acc11, lo, hi);
    Cb[row * D_ + col + 1] = lo + bn1;   Cb[(row + 1) * D_ + col + 1] = hi + bn1;
}

// ---------------------------------------------------------------------------
// M2[a][l][d] = sum_e W2[g2[a]][d][e] * Wh[a][e][l], binned by g2.
// Grid (8 g2, 24 d-tiles of 32), 256 threads = 32 d x 8 annotator slots.
// ---------------------------------------------------------------------------
__global__ void __launch_bounds__(256) m2_kernel(const float* __restrict__ W2,
                                                 const float* __restrict__ Wh) {
    const int g2 = blockIdx.x;
    const int d0 = blockIdx.y * 32;
    const float* W2g = W2 + g2 * D_ * D_;
    const int nS = g_cnt[g2];
    if (nS == 0) return;

    __shared__ __align__(16) float W2s[32][36];   // [d][e], padded
    __shared__ __align__(16) float Whs[64][68];   // [local_a][2e interleaved l], padded

    const int t  = threadIdx.x;
    const int d  = t >> 3;          // 0..31
    const int as = t & 7;           // 0..7

    const int ld_e = (t & 7) * 4;   // W2 tile load: same d = t>>3

    for (int abase = 0; abase < nS; abase += 64) {
        const int nb  = min(64, nS - abase);
        const int njb = (nb + 7) >> 3;

        unsigned long long acc[8];
#pragma unroll
        for (int j = 0; j < 8; j++) acc[j] = 0ull;

        for (int e0 = 0; e0 < D_; e0 += 32) {
            *(float4*)&W2s[d][ld_e] = *(const float4*)(W2g + (d0 + d) * D_ + e0 + ld_e);
#pragma unroll
            for (int i = 0; i < 4; i++) {
                int fidx = i * 256 + t;
                int row  = fidx >> 4;
                int rem  = fidx & 15;
                float4 v = make_float4(0.f, 0.f, 0.f, 0.f);
                if (row < nb) {
                    int a = g_list[g2][abase + row];
                    v = *(const float4*)(Wh + a * (D_ * L_) + e0 * 2 + rem * 4);
                }
                *(float4*)&Whs[row][rem * 4] = v;
            }
            __syncthreads();
#pragma unroll
            for (int eq = 0; eq < 8; eq++) {
                float4 wq = *(const float4*)&W2s[d][eq * 4];
                unsigned long long wp0 = pack2(wq.x, wq.x);
                unsigned long long wp1 = pack2(wq.y, wq.y);
                unsigned long long wp2 = pack2(wq.z, wq.z);
                unsigned long long wp3 = pack2(wq.w, wq.w);
                for (int j = 0; j < njb; j++) {
                    const float* wrow = &Whs[as + j * 8][eq * 8];
                    ulonglong2 wa = *(const ulonglong2*)(wrow);
                    ulonglong2 wb = *(const ulonglong2*)(wrow + 4);
                    ffma2(acc[j], wp0, wa.x);
                    ffma2(acc[j], wp1, wa.y);
                    ffma2(acc[j], wp2, wb.x);
                    ffma2(acc[j], wp3, wb.y);
                }
            }
            __syncthreads();
        }

        for (int j = 0; j < njb; j++) {
            int loc = as + j * 8;
            if (loc < nb) {
                int a = g_list[g2][abase + loc];
                float lo, hi;
                unpack2(acc[j], lo, hi);
                g_M2[a * (L_ * D_) + d0 + d]      = lo;
                g_M2[a * (L_ * D_) + D_ + d0 + d] = hi;
            }
        }
    }
}

// ---------------------------------------------------------------------------
// out[b][a][l] = sum_d h1[g1[a]][b][d] * M2[a][l][d] + c[a][l]
// One block per annotator, 8 warps, warp per b-row (strided).
// ---------------------------------------------------------------------------
__global__ void __launch_bounds__(256) heads_kernel(const int* __restrict__ g1i,
                                                    float* __restrict__ out) {
    const int a = blockIdx.x;
    __shared__ __align__(16) float m2s[2 * D_];
    const int t = threadIdx.x;
#pragma unroll
    for (int i = 0; i < (2 * D_) / (4 * 256) + 1; i++) {
        int f = (i * 256 + t) * 4;
        if (f < 2 * D_)
            *(float4*)&m2s[f] = *(const float4*)&g_M2[a * (2 * D_) + f];
    }
    __syncthreads();

    const int g1 = g1i[a];
    const float c0 = g_c[a * 2], c1 = g_c[a * 2 + 1];
    const float* h = g_h1 + g1 * B_ * D_;
    const int warp = t >> 5, lane = t & 31;

    for (int b = warp; b < B_; b += 8) {
        const float* hb = h + b * D_;
        float s0 = 0.f, s1 = 0.f;
#pragma unroll
        for (int i = 0; i < 6; i++) {
            int dd = i * 128 + lane * 4;
            float4 hv = *(const float4*)(hb + dd);
            float4 m0 = *(const float4*)&m2s[dd];
            float4 m1 = *(const float4*)&m2s[D_ + dd];
            s0 += hv.x * m0.x + hv.y * m0.y + hv.z * m0.z + hv.w * m0.w;
            s1 += hv.x * m1.x + hv.y * m1.y + hv.z * m1.z + hv.w * m1.w;
        }
#pragma unroll
        for (int o = 16; o; o >>= 1) {
            s0 += __shfl_down_sync(~0u, s0, o);
            s1 += __shfl_down_sync(~0u, s1, o);
        }
        if (lane == 0) {
            out[(b * A_ + a) * L_ + 0] = s0 + c0;
            out[(b * A_ + a) * L_ + 1] = s1 + c1;
        }
    }
}

extern "C" void kernel_launch(void* const* d_in, const int* in_sizes, int n_in,
                              void* d_out, int out_size) {
    const float* pooled = (const float*)d_in[0];
    const float* W1     = (const float*)d_in[1];
    const float* b1     = (const float*)d_in[2];
    const float* W2     = (const float*)d_in[3];
    const float* b2     = (const float*)d_in[4];
    const float* Wh     = (const float*)d_in[5];
    const float* bh     = (const float*)d_in[6];
    const int*   g1i    = (const int*)d_in[7];
    const int*   g2i    = (const int*)d_in[8];
    float* out = (float*)d_out;

    bin_kernel<<<1, 32>>>(g2i);
    stage1_kernel<<<dim3(D_ / 32, 2, NG1), 128>>>(pooled, W1, b1);
    c_kernel<<<A_, 128>>>(b2, Wh, bh, g2i);
    m2_kernel<<<dim3(NG2, D_ / 32), 256>>>(W2, Wh);
    heads_kernel<<<A_, 256>>>(g1i, out);
}

// round 3
// speedup vs baseline: 1.9401x; 1.9401x over previous
#include <cuda_runtime.h>

#define D_ 768
#define B_ 64
#define A_ 256
#define L_ 2
#define NG1 4
#define NG2 8
#define BHW 608            // padded column width of packed Wh matrix
#define KHALF (D_ / 2)     // split-K halves for m2
#define S1_BLOCKS (24 * NG1)

// Scratch (zero-initialized .bss; never freed/alloc'd)
__device__ float g_h1[NG1 * B_ * D_];          // [g1][b][d]
__device__ float g_Bh[D_ * BHW];               // packed Wh columns [e][col]
__device__ float g_M2s[2][A_ * L_ * D_];       // split-K partials [s][a][l][d]
__device__ float g_c[A_ * L_];                 // fused bias b2@Wh + bh
__device__ int   g_slot2a[NG2 * A_];           // (bin, local slot) -> annotator

__device__ __forceinline__ void ffma2(unsigned long long& acc,
                                      unsigned long long a,
                                      unsigned long long b) {
    asm("fma.rn.f32x2 %0, %1, %2, %0;" : "+l"(acc) : "l"(a), "l"(b));
}
__device__ __forceinline__ unsigned long long pack2(float lo, float hi) {
    unsigned long long r;
    asm("mov.b64 %0, {%1, %2};" : "=l"(r) : "f"(lo), "f"(hi));
    return r;
}
__device__ __forceinline__ void unpack2(unsigned long long v, float& lo, float& hi) {
    asm("mov.b64 {%0, %1}, %2;" : "=f"(lo), "=f"(hi) : "l"(v));
}

// ---------------------------------------------------------------------------
// Prep: per annotator, compute its packed column position (scan of g2i),
// scatter Wh[a] into g_Bh, record slot->a map, and compute the fused bias
// c[a][l] = b2[g2[a]] . Wh[a][:,l] + bh[a][l].
// ---------------------------------------------------------------------------
__global__ void __launch_bounds__(256) gather_kernel(const float* __restrict__ Wh,
                                                     const float* __restrict__ b2,
                                                     const float* __restrict__ bh,
                                                     const int* __restrict__ g2i) {
    const int a = blockIdx.x;
    const int t = threadIdx.x;
    __shared__ int sg[A_];
    __shared__ int s_col0;
    __shared__ float red[8][2];

    sg[t] = g2i[t];
    __syncthreads();
    if (t == 0) {
        const int g = sg[a];
        int cnt[NG2];
#pragma unroll
        for (int j = 0; j < NG2; j++) cnt[j] = 0;
        int slot = 0;
        for (int i = 0; i < A_; i++) {
            int gi = sg[i];
            if (gi == g && i < a) slot++;
            cnt[gi]++;
        }
        int off = 0;
#pragma unroll
        for (int j = 0; j < NG2; j++)
            if (j < g) off += (cnt[j] + 1) & ~1;   // even-align each bin
        s_col0 = 2 * (off + slot);
        g_slot2a[g * A_ + slot] = a;
    }
    __syncthreads();

    const int col0 = s_col0;
    const int g = sg[a];
    const float* wha = Wh + a * (D_ * L_);
    const float* b2g = b2 + g * D_;

    float s0 = 0.f, s1 = 0.f;
#pragma unroll
    for (int i = 0; i < D_ / 256; i++) {
        int e = i * 256 + t;
        float2 w = *(const float2*)(wha + 2 * e);
        *(float2*)(g_Bh + e * BHW + col0) = w;
        float bv = b2g[e];
        s0 += bv * w.x;
        s1 += bv * w.y;
    }
#pragma unroll
    for (int o = 16; o; o >>= 1) {
        s0 += __shfl_down_sync(~0u, s0, o);
        s1 += __shfl_down_sync(~0u, s1, o);
    }
    const int warp = t >> 5, lane = t & 31;
    if (lane == 0) { red[warp][0] = s0; red[warp][1] = s1; }
    __syncthreads();
    if (t == 0) {
        float a0 = 0.f, a1 = 0.f;
#pragma unroll
        for (int w = 0; w < 8; w++) { a0 += red[w][0]; a1 += red[w][1]; }
        g_c[a * 2 + 0] = a0 + bh[a * 2 + 0];
        g_c[a * 2 + 1] = a1 + bh[a * 2 + 1];
    }
}

// ---------------------------------------------------------------------------
// Fat GEMM kernel: blocks [0,96) do stage1 (h1 = pooled @ W1[g] + b1),
// blocks [96,864) do M2 (= W2[g2] @ packed-Wh), split-K = 2.
// Common scheme: 256 thr, BM=64, BK=16, f32x2 with N-pair accumulators:
// A stored DUPLICATED in smem (a,a), B read directly as pairs -> zero packing.
// ---------------------------------------------------------------------------
__global__ void __launch_bounds__(256) fat_gemm(const float* __restrict__ pooled,
                                                const float* __restrict__ W1,
                                                const float* __restrict__ b1,
                                                const float* __restrict__ W2,
                                                const int* __restrict__ g2i) {
    __shared__ __align__(16) float Asd[16][132];   // duplicated A: [k][2*m]
    __shared__ __align__(16) float Bsn[16][68];    // plain B tile: [k][n]

    const int t   = threadIdx.x;
    const int mg  = t >> 4;         // 0..15, 4 m-rows each
    const int ng  = t & 15;         // 0..15
    const int arow = t >> 2;        // A loader: row 0..63
    const int akq  = (t & 3) * 4;   // A loader: k quad

    if (blockIdx.x < S1_BLOCKS) {
        // ================= stage 1: h1[g] = pooled @ W1[g] + b1[g] ==========
        const int nt = blockIdx.x % 24;
        const int g  = blockIdx.x / 24;
        const int n0 = nt * 32;
        const float* Wg = W1 + g * D_ * D_;
        const bool bload = t < 128;
        const int kr = (t & 127) >> 3;
        const int nc = (t & 7) * 4;
        const float* aptr = pooled + arow * D_ + akq;
        const float* wptr = Wg + kr * D_ + n0 + nc;

        float4 pa = *(const float4*)aptr;
        float4 pw = bload ? *(const float4*)wptr : make_float4(0.f, 0.f, 0.f, 0.f);

        unsigned long long acc[4];
#pragma unroll
        for (int m = 0; m < 4; m++) acc[m] = 0ull;

        for (int k0 = 0; k0 < D_; k0 += 16) {
            *(unsigned long long*)&Asd[akq + 0][arow * 2] = pack2(pa.x, pa.x);
            *(unsigned long long*)&Asd[akq + 1][arow * 2] = pack2(pa.y, pa.y);
            *(unsigned long long*)&Asd[akq + 2][arow * 2] = pack2(pa.z, pa.z);
            *(unsigned long long*)&Asd[akq + 3][arow * 2] = pack2(pa.w, pa.w);
            if (bload) *(float4*)&Bsn[kr][nc] = pw;
            __syncthreads();
            if (k0 + 16 < D_) {
                pa = *(const float4*)(aptr + k0 + 16);
                if (bload) pw = *(const float4*)(wptr + (k0 + 16) * D_);
            }
#pragma unroll
            for (int kk = 0; kk < 16; kk++) {
                ulonglong2 ad  = *(const ulonglong2*)&Asd[kk][mg * 8];
                ulonglong2 ad2 = *(const ulonglong2*)&Asd[kk][mg * 8 + 4];
                unsigned long long bp = *(const unsigned long long*)&Bsn[kk][ng * 2];
                ffma2(acc[0], ad.x,  bp);
                ffma2(acc[1], ad.y,  bp);
                ffma2(acc[2], ad2.x, bp);
                ffma2(acc[3], ad2.y, bp);
            }
            __syncthreads();
        }

        float* Cb = g_h1 + g * B_ * D_;
        const int col = n0 + ng * 2;
        const float bn0 = b1[g * D_ + col];
        const float bn1 = b1[g * D_ + col + 1];
#pragma unroll
        for (int m = 0; m < 4; m++) {
            float c0, c1;
            unpack2(acc[m], c0, c1);
            const int row = mg * 4 + m;
            Cb[row * D_ + col]     = c0 + bn0;
            Cb[row * D_ + col + 1] = c1 + bn1;
        }
    } else {
        // ================= M2: C[d][col] = W2[g] @ Bh (split-K) =============
        const int bid = blockIdx.x - S1_BLOCKS;
        const int g   = bid & 7;
        const int dt  = (bid >> 3) % 12;
        const int cs  = (bid / 96) & 3;
        const int s   = bid / 384;              // split-K half

        __shared__ int scnt[NG2];
        __shared__ int s_off, s_cnt;
        if (t < NG2) scnt[t] = 0;
        __syncthreads();
        atomicAdd(&scnt[g2i[t]], 1);
        __syncthreads();
        if (t == 0) {
            int off = 0;
#pragma unroll
            for (int j = 0; j < NG2; j++)
                if (j < g) off += (scnt[j] + 1) & ~1;
            s_off = off;
            s_cnt = scnt[g];
        }
        __syncthreads();

        const int ncols = 2 * s_cnt;
        const int cbg0  = 2 * s_off;
        const int d0    = dt * 64;
        const int e_st  = s * KHALF;
        const float* W2g = W2 + g * D_ * D_;
        const int kr = t >> 4;
        const int cq = (t & 15) * 4;

        for (int cb = cs * 64; cb < ncols; cb += 256) {
            unsigned long long acc[4][2];
#pragma unroll
            for (int m = 0; m < 4; m++)
#pragma unroll
                for (int np = 0; np < 2; np++) acc[m][np] = 0ull;

            const float* aptr = W2g + (d0 + arow) * D_ + e_st + akq;
            const float* bptr = g_Bh + (e_st + kr) * BHW + cbg0 + cb + cq;
            float4 pa = *(const float4*)aptr;
            float4 pb = *(const float4*)bptr;

            for (int e0 = 0; e0 < KHALF; e0 += 16) {
                *(unsigned long long*)&Asd[akq + 0][arow * 2] = pack2(pa.x, pa.x);
                *(unsigned long long*)&Asd[akq + 1][arow * 2] = pack2(pa.y, pa.y);
                *(unsigned long long*)&Asd[akq + 2][arow * 2] = pack2(pa.z, pa.z);
                *(unsigned long long*)&Asd[akq + 3][arow * 2] = pack2(pa.w, pa.w);
                *(float4*)&Bsn[kr][cq] = pb;
                __syncthreads();
                if (e0 + 16 < KHALF) {
                    pa = *(const float4*)(aptr + e0 + 16);
                    pb = *(const float4*)(bptr + (e0 + 16) * BHW);
                }
#pragma unroll
                for (int kk = 0; kk < 16; kk++) {
                    ulonglong2 ad  = *(const ulonglong2*)&Asd[kk][mg * 8];
                    ulonglong2 ad2 = *(const ulonglong2*)&Asd[kk][mg * 8 + 4];
                    ulonglong2 bp  = *(const ulonglong2*)&Bsn[kk][ng * 4];
                    ffma2(acc[0][0], ad.x,  bp.x);
                    ffma2(acc[0][1], ad.x,  bp.y);
                    ffma2(acc[1][0], ad.y,  bp.x);
                    ffma2(acc[1][1], ad.y,  bp.y);
                    ffma2(acc[2][0], ad2.x, bp.x);
                    ffma2(acc[2][1], ad2.x, bp.y);
                    ffma2(acc[3][0], ad2.y, bp.x);
                    ffma2(acc[3][1], ad2.y, bp.y);
                }
                __syncthreads();
            }

            // epilogue: col pair (c, c+1) = annotator slot (l=0, l=1)
#pragma unroll
            for (int np = 0; np < 2; np++) {
                const int c = cb + ng * 4 + np * 2;   // even
                if (c < ncols) {
                    const int a = g_slot2a[g * A_ + (c >> 1)];
                    float* o0 = &g_M2s[s][(a * 2 + 0) * D_ + d0 + mg * 4];
                    float* o1 = &g_M2s[s][(a * 2 + 1) * D_ + d0 + mg * 4];
#pragma unroll
                    for (int m = 0; m < 4; m++) {
                        float v0, v1;
                        unpack2(acc[m][np], v0, v1);
                        o0[m] = v0;
                        o1[m] = v1;
                    }
                }
            }
        }
    }
}

// ---------------------------------------------------------------------------
// Heads: out[b][a][l] = h1[g1[a]][b][:] . M2[a][l][:] + c[a][l]
// M2 = sum of the two split-K partials (added while staging into smem).
// ---------------------------------------------------------------------------
__global__ void __launch_bounds__(256) heads_kernel(const int* __restrict__ g1i,
                                                    float* __restrict__ out) {
    const int a = blockIdx.x;
    const int t = threadIdx.x;
    __shared__ __align__(16) float m2s[L_ * D_];

#pragma unroll
    for (int i = 0; i < 2; i++) {
        int idx = i * 256 + t;
        if (idx < (L_ * D_) / 4) {
            float4 v0 = *(const float4*)&g_M2s[0][a * (L_ * D_) + idx * 4];
            float4 v1 = *(const float4*)&g_M2s[1][a * (L_ * D_) + idx * 4];
            v0.x += v1.x; v0.y += v1.y; v0.z += v1.z; v0.w += v1.w;
            *(float4*)&m2s[idx * 4] = v0;
        }
    }
    __syncthreads();

    const int g1 = g1i[a];
    const float c0 = g_c[a * 2], c1 = g_c[a * 2 + 1];
    const float* h = g_h1 + g1 * B_ * D_;
    const int warp = t >> 5, lane = t & 31;

    for (int b = warp; b < B_; b += 8) {
        const float* hb = h + b * D_;
        float s0 = 0.f, s1 = 0.f;
#pragma unroll
        for (int i = 0; i < 6; i++) {
            int dd = i * 128 + lane * 4;
            float4 hv = *(const float4*)(hb + dd);
            float4 m0 = *(const float4*)&m2s[dd];
            float4 m1 = *(const float4*)&m2s[D_ + dd];
            s0 += hv.x * m0.x + hv.y * m0.y + hv.z * m0.z + hv.w * m0.w;
            s1 += hv.x * m1.x + hv.y * m1.y + hv.z * m1.z + hv.w * m1.w;
        }
#pragma unroll
        for (int o = 16; o; o >>= 1) {
            s0 += __shfl_down_sync(~0u, s0, o);
            s1 += __shfl_down_sync(~0u, s1, o);
        }
        if (lane == 0) {
            out[(b * A_ + a) * L_ + 0] = s0 + c0;
            out[(b * A_ + a) * L_ + 1] = s1 + c1;
        }
    }
}

extern "C" void kernel_launch(void* const* d_in, const int* in_sizes, int n_in,
                              void* d_out, int out_size) {
    const float* pooled = (const float*)d_in[0];
    const float* W1     = (const float*)d_in[1];
    const float* b1     = (const float*)d_in[2];
    const float* W2     = (const float*)d_in[3];
    const float* b2     = (const float*)d_in[4];
    const float* Wh     = (const float*)d_in[5];
    const float* bh     = (const float*)d_in[6];
    const int*   g1i    = (const int*)d_in[7];
    const int*   g2i    = (const int*)d_in[8];
    float* out = (float*)d_out;

    gather_kernel<<<A_, 256>>>(Wh, b2, bh, g2i);
    fat_gemm<<<S1_BLOCKS + NG2 * 12 * 4 * 2, 256>>>(pooled, W1, b1, W2, g2i);
    heads_kernel<<<A_, 256>>>(g1i, out);
}

// round 4
// speedup vs baseline: 2.6267x; 1.3539x over previous
#include <cuda_runtime.h>

#define D_ 768
#define B_ 64
#define A_ 256
#define L_ 2
#define NG1 4
#define NG2 8
#define BHW 704                 // packed Wh row width (worst-case colbase+128 fits)
#define NSPLIT 4
#define KS (D_ / NSPLIT)        // 192
#define NCH (KS / 16)           // 12 chunks per split

// ---- scratch (.bss device globals; zero-initialized once, never freed) ----
__device__ float g_h1p[NSPLIT][NG1 * B_ * D_];   // stage1 split-K partials
__device__ float g_h1[NG1 * B_ * D_];            // summed h1
__device__ float g_Bh[D_ * BHW];                 // packed Wh columns [e][col]
__device__ float g_M2p[NSPLIT][A_ * L_ * D_];    // M2 split-K partials [a][l][d]
__device__ int   g_slot2a[NG2 * A_];
__device__ int   g_binoff[NG2];
__device__ int   g_bincnt[NG2];

__device__ __forceinline__ void ffma2(unsigned long long& acc,
                                      unsigned long long a,
                                      unsigned long long b) {
    asm("fma.rn.f32x2 %0, %1, %2, %0;" : "+l"(acc) : "l"(a), "l"(b));
}
__device__ __forceinline__ unsigned long long pack2(float lo, float hi) {
    unsigned long long r;
    asm("mov.b64 %0, {%1, %2};" : "=l"(r) : "f"(lo), "f"(hi));
    return r;
}
__device__ __forceinline__ void unpack2(unsigned long long v, float& lo, float& hi) {
    asm("mov.b64 {%0, %1}, %2;" : "=f"(lo), "=f"(hi) : "l"(v));
}

// ---------------------------------------------------------------------------
// Prep (1 block): per-annotator slot within its g2 bin, bin offsets/counts.
// ---------------------------------------------------------------------------
__global__ void __launch_bounds__(256) prep_kernel(const int* __restrict__ g2i) {
    const int t = threadIdx.x;
    __shared__ int sg[A_];
    __shared__ int cnt[NG2];
    __shared__ int off[NG2];
    sg[t] = g2i[t];
    __syncthreads();
    const int g = sg[t];
    int slot = 0;
    for (int i = 0; i < t; i++) slot += (sg[i] == g);
    if (t < NG2) {
        int c = 0;
        for (int i = 0; i < A_; i++) c += (sg[i] == t);
        cnt[t] = c;
    }
    __syncthreads();
    if (t == 0) {
        int o = 0;
        for (int j = 0; j < NG2; j++) { off[j] = o; o += (2 * cnt[j] + 7) & ~7; }
    }
    __syncthreads();
    g_slot2a[g * A_ + slot] = t;
    if (t < NG2) { g_binoff[t] = off[t]; g_bincnt[t] = cnt[t]; }
}

// ---------------------------------------------------------------------------
// Gather: pack Wh into g_Bh[e][col] via smem tile transpose.
// Grid (NG2, 12 e-tiles of 64). Coalesced reads AND writes.
// ---------------------------------------------------------------------------
__global__ void __launch_bounds__(256) gather_kernel(const float* __restrict__ Wh) {
    const int g  = blockIdx.x;
    const int e0 = blockIdx.y * 64;
    const int cnt = g_bincnt[g];
    const int off = g_binoff[g];
    if (cnt == 0) return;

    __shared__ float stile[64][98];
    const int t = threadIdx.x;
    const int warp = t >> 5, lane = t & 31;

    for (int sb = 0; sb < cnt; sb += 48) {
        const int nsl = min(48, cnt - sb);
        // phase A: one warp per slot; lane reads float4 of Wh (coalesced)
        for (int s = warp; s < nsl; s += 8) {
            const int a = g_slot2a[g * A_ + sb + s];
            float4 v = *(const float4*)(Wh + a * (D_ * L_) + e0 * 2 + lane * 4);
            const int er = lane * 2;
            stile[er][2 * s]         = v.x;
            stile[er][2 * s + 1]     = v.y;
            stile[er + 1][2 * s]     = v.z;
            stile[er + 1][2 * s + 1] = v.w;
        }
        __syncthreads();
        // phase B: write g_Bh rows (coalesced float2)
        const int w2 = nsl;                        // float2 per row
        for (int idx = t; idx < 64 * w2; idx += 256) {
            const int r = idx / w2, c2 = idx % w2;
            float2 v = *(const float2*)&stile[r][c2 * 2];
            *(float2*)(g_Bh + (e0 + r) * BHW + off + sb * 2 + c2 * 2) = v;
        }
        __syncthreads();
    }
}

// ---------------------------------------------------------------------------
// Unified 64x64xKS GEMM body. 256 thr, BK=16, double-buffered smem,
// register prefetch, f32x2 N-pair accumulators (A pre-duplicated in smem).
// ---------------------------------------------------------------------------
__device__ __forceinline__ void gemm64(const float* __restrict__ Ab, int lda,
                                       const float* __restrict__ Bb, int ldb,
                                       float Asd[2][16][132],
                                       float Bsn[2][16][68],
                                       unsigned long long acc[4][2]) {
    const int t = threadIdx.x;
    const int mg = t >> 4, ng = t & 15;
    const int arow = t >> 2, akq = (t & 3) * 4;
    const int kr = t >> 4, cq = (t & 15) * 4;
    const float* aptr = Ab + arow * lda + akq;
    const float* bptr = Bb + kr * ldb + cq;

#pragma unroll
    for (int m = 0; m < 4; m++) { acc[m][0] = 0ull; acc[m][1] = 0ull; }

    float4 pa = *(const float4*)aptr;
    float4 pb = *(const float4*)bptr;
    *(unsigned long long*)&Asd[0][akq + 0][arow * 2] = pack2(pa.x, pa.x);
    *(unsigned long long*)&Asd[0][akq + 1][arow * 2] = pack2(pa.y, pa.y);
    *(unsigned long long*)&Asd[0][akq + 2][arow * 2] = pack2(pa.z, pa.z);
    *(unsigned long long*)&Asd[0][akq + 3][arow * 2] = pack2(pa.w, pa.w);
    *(float4*)&Bsn[0][kr][cq] = pb;
    __syncthreads();
    pa = *(const float4*)(aptr + 16);
    pb = *(const float4*)(bptr + 16 * ldb);

#pragma unroll 1
    for (int c = 0; c < NCH; c++) {
        const int cur = c & 1;
        if (c + 1 < NCH) {
            const int nxt = cur ^ 1;
            *(unsigned long long*)&Asd[nxt][akq + 0][arow * 2] = pack2(pa.x, pa.x);
            *(unsigned long long*)&Asd[nxt][akq + 1][arow * 2] = pack2(pa.y, pa.y);
            *(unsigned long long*)&Asd[nxt][akq + 2][arow * 2] = pack2(pa.z, pa.z);
            *(unsigned long long*)&Asd[nxt][akq + 3][arow * 2] = pack2(pa.w, pa.w);
            *(float4*)&Bsn[nxt][kr][cq] = pb;
        }
#pragma unroll
        for (int kk = 0; kk < 16; kk++) {
            ulonglong2 ad  = *(const ulonglong2*)&Asd[cur][kk][mg * 8];
            ulonglong2 ad2 = *(const ulonglong2*)&Asd[cur][kk][mg * 8 + 4];
            ulonglong2 bp  = *(const ulonglong2*)&Bsn[cur][kk][ng * 4];
            ffma2(acc[0][0], ad.x,  bp.x);
            ffma2(acc[0][1], ad.x,  bp.y);
            ffma2(acc[1][0], ad.y,  bp.x);
            ffma2(acc[1][1], ad.y,  bp.y);
            ffma2(acc[2][0], ad2.x, bp.x);
            ffma2(acc[2][1], ad2.x, bp.y);
            ffma2(acc[3][0], ad2.y, bp.x);
            ffma2(acc[3][1], ad2.y, bp.y);
        }
        __syncthreads();
        if (c + 2 < NCH) {
            pa = *(const float4*)(aptr + (c + 2) * 16);
            pb = *(const float4*)(bptr + (c + 2) * 16 * ldb);
        }
    }
}

// ---------------------------------------------------------------------------
// Fat GEMM: blocks [0,192) stage1 split-K partials; [192,960) M2 split-K.
// ---------------------------------------------------------------------------
__global__ void __launch_bounds__(256) fat_gemm(const float* __restrict__ pooled,
                                                const float* __restrict__ W1,
                                                const float* __restrict__ b1,
                                                const float* __restrict__ W2) {
    __shared__ __align__(16) float Asd[2][16][132];
    __shared__ __align__(16) float Bsn[2][16][68];
    unsigned long long acc[4][2];

    const int t = threadIdx.x;
    const int mg = t >> 4, ng = t & 15;
    const int bx = blockIdx.x;

    if (bx < 192) {
        // ---- stage1 partial: h1p[s][g] = pooled[:, sK] @ W1[g][sK, n-tile] ----
        const int nt = bx % 12;
        const int g  = (bx / 12) & 3;
        const int s  = bx / 48;
        const int n0 = nt * 64;
        const int e0 = s * KS;
        gemm64(pooled + e0, D_, W1 + g * D_ * D_ + e0 * D_ + n0, D_, Asd, Bsn, acc);

        float* Cb = g_h1p[s] + g * B_ * D_;
        const int col = n0 + ng * 4;
        float4 bb = make_float4(0.f, 0.f, 0.f, 0.f);
        if (s == 0) bb = *(const float4*)(b1 + g * D_ + col);
#pragma unroll
        for (int m = 0; m < 4; m++) {
            float4 v;
            unpack2(acc[m][0], v.x, v.y);
            unpack2(acc[m][1], v.z, v.w);
            v.x += bb.x; v.y += bb.y; v.z += bb.z; v.w += bb.w;
            *(float4*)(Cb + (mg * 4 + m) * D_ + col) = v;
        }
    } else {
        // ---- M2 partial: W2[g][d-tile, sK] @ g_Bh[sK, col-tile] ----
        const int idx = bx - 192;
        const int g   = idx & 7;
        const int dt  = (idx >> 3) % 12;
        const int ct  = (idx / 96) & 1;
        const int s   = idx / 192;

        const int ncols = 2 * g_bincnt[g];
        const int cb    = ct * 64;
        if (cb >= ncols) return;
        const int colbase = g_binoff[g];
        const int d0 = dt * 64;
        const int e0 = s * KS;

        gemm64(W2 + g * D_ * D_ + d0 * D_ + e0, D_,
               g_Bh + e0 * BHW + colbase + cb, BHW, Asd, Bsn, acc);

#pragma unroll
        for (int np = 0; np < 2; np++) {
            const int c = cb + ng * 4 + np * 2;     // even: (slot=c/2, l=0|1)
            if (c < ncols) {
                const int a = g_slot2a[g * A_ + (c >> 1)];
                float4 v0, v1;
                unpack2(acc[0][np], v0.x, v1.x);
                unpack2(acc[1][np], v0.y, v1.y);
                unpack2(acc[2][np], v0.z, v1.z);
                unpack2(acc[3][np], v0.w, v1.w);
                *(float4*)(g_M2p[s] + (a * 2 + 0) * D_ + d0 + mg * 4) = v0;
                *(float4*)(g_M2p[s] + (a * 2 + 1) * D_ + d0 + mg * 4) = v1;
            }
        }
    }
}

// ---------------------------------------------------------------------------
// Sum the 4 stage1 split-K partials into g_h1. 192 blocks x 256 thr x float4.
// ---------------------------------------------------------------------------
__global__ void __launch_bounds__(256) sumh1_kernel() {
    const int i = (blockIdx.x * 256 + threadIdx.x) * 4;
    float4 v0 = *(const float4*)(g_h1p[0] + i);
    float4 v1 = *(const float4*)(g_h1p[1] + i);
    float4 v2 = *(const float4*)(g_h1p[2] + i);
    float4 v3 = *(const float4*)(g_h1p[3] + i);
    v0.x += v1.x + v2.x + v3.x;
    v0.y += v1.y + v2.y + v3.y;
    v0.z += v1.z + v2.z + v3.z;
    v0.w += v1.w + v2.w + v3.w;
    *(float4*)(g_h1 + i) = v0;
}

// ---------------------------------------------------------------------------
// Heads: out[b][a][l] = h1[g1[a]][b][:] . M2[a][l][:] + (b2[g2].Wh[a][:,l] + bh)
// M2 summed from 4 partials while staging into smem; c-bias computed inline.
// ---------------------------------------------------------------------------
__global__ void __launch_bounds__(256) heads_kernel(const float* __restrict__ b2,
                                                    const float* __restrict__ Wh,
                                                    const float* __restrict__ bh,
                                                    const int* __restrict__ g1i,
                                                    const int* __restrict__ g2i,
                                                    float* __restrict__ out) {
    const int a = blockIdx.x;
    const int t = threadIdx.x;
    __shared__ __align__(16) float m2s[L_ * D_];
    __shared__ float cred[8][2];
    __shared__ float cc[2];

#pragma unroll
    for (int i = 0; i < 2; i++) {
        const int f = (i * 256 + t) * 4;
        if (f < L_ * D_) {
            float4 v0 = *(const float4*)(g_M2p[0] + a * (L_ * D_) + f);
            float4 v1 = *(const float4*)(g_M2p[1] + a * (L_ * D_) + f);
            float4 v2 = *(const float4*)(g_M2p[2] + a * (L_ * D_) + f);
            float4 v3 = *(const float4*)(g_M2p[3] + a * (L_ * D_) + f);
            v0.x += v1.x + v2.x + v3.x;
            v0.y += v1.y + v2.y + v3.y;
            v0.z += v1.z + v2.z + v3.z;
            v0.w += v1.w + v2.w + v3.w;
            *(float4*)&m2s[f] = v0;
        }
    }

    // fused bias: c[l] = b2[g2] . Wh[a][:,l] + bh[a][l]
    const int g2 = g2i[a];
    float s0 = 0.f, s1 = 0.f;
#pragma unroll
    for (int i = 0; i < 3; i++) {
        const int e = i * 256 + t;
        const float bv = b2[g2 * D_ + e];
        float2 w = *(const float2*)(Wh + a * (D_ * L_) + 2 * e);
        s0 += bv * w.x;
        s1 += bv * w.y;
    }
#pragma unroll
    for (int o = 16; o; o >>= 1) {
        s0 += __shfl_down_sync(~0u, s0, o);
        s1 += __shfl_down_sync(~0u, s1, o);
    }
    const int warp = t >> 5, lane = t & 31;
    if (lane == 0) { cred[warp][0] = s0; cred[warp][1] = s1; }
    __syncthreads();
    if (t == 0) {
        float a0 = 0.f, a1 = 0.f;
#pragma unroll
        for (int w = 0; w < 8; w++) { a0 += cred[w][0]; a1 += cred[w][1]; }
        cc[0] = a0 + bh[a * 2 + 0];
        cc[1] = a1 + bh[a * 2 + 1];
    }
    __syncthreads();

    const float c0 = cc[0], c1 = cc[1];
    const float* h = g_h1 + g1i[a] * B_ * D_;

    for (int b = warp; b < B_; b += 8) {
        const float* hb = h + b * D_;
        float r0 = 0.f, r1 = 0.f;
#pragma unroll
        for (int i = 0; i < 6; i++) {
            const int dd = i * 128 + lane * 4;
            float4 hv = *(const float4*)(hb + dd);
            float4 m0 = *(const float4*)&m2s[dd];
            float4 m1 = *(const float4*)&m2s[D_ + dd];
            r0 += hv.x * m0.x + hv.y * m0.y + hv.z * m0.z + hv.w * m0.w;
            r1 += hv.x * m1.x + hv.y * m1.y + hv.z * m1.z + hv.w * m1.w;
        }
#pragma unroll
        for (int o = 16; o; o >>= 1) {
            r0 += __shfl_down_sync(~0u, r0, o);
            r1 += __shfl_down_sync(~0u, r1, o);
        }
        if (lane == 0) {
            out[(b * A_ + a) * L_ + 0] = r0 + c0;
            out[(b * A_ + a) * L_ + 1] = r1 + c1;
        }
    }
}

extern "C" void kernel_launch(void* const* d_in, const int* in_sizes, int n_in,
                              void* d_out, int out_size) {
    const float* pooled = (const float*)d_in[0];
    const float* W1     = (const float*)d_in[1];
    const float* b1     = (const float*)d_in[2];
    const float* W2     = (const float*)d_in[3];
    const float* b2     = (const float*)d_in[4];
    const float* Wh     = (const float*)d_in[5];
    const float* bh     = (const float*)d_in[6];
    const int*   g1i    = (const int*)d_in[7];
    const int*   g2i    = (const int*)d_in[8];
    float* out = (float*)d_out;

    prep_kernel<<<1, 256>>>(g2i);
    gather_kernel<<<dim3(NG2, 12), 256>>>(Wh);
    fat_gemm<<<192 + 768, 256>>>(pooled, W1, b1, W2);
    sumh1_kernel<<<192, 256>>>();
    heads_kernel<<<A_, 256>>>(b2, Wh, bh, g1i, g2i, out);
}